// round 14
// baseline (speedup 1.0000x reference)
#include <cuda_runtime.h>
#include <cuda_fp16.h>
#include <math.h>

#define VD 256
#define VH 240
#define VW 320
#define NPIX (VH * VW)
#define XB (VW / 32)      // 10 x-blocks of 32 x (= 16 xp)

// Density volume, fp16, 2x2 (x,z)-quad cells, non-redundant, 39.3 MB.
// Cell (y, xp, zp) as 64-bit word, bit offset of corner (xo, zo) = xo*32+zo*16:
//   bits[ 0:16) E(2xp,  2zp)   bits[16:32) E(2xp,  2zp+1)
//   bits[32:48) E(2xp+1,2zp)   bits[48:64) E(2xp+1,2zp+1)
// index = ((y*XB + (xp>>4))*128 + zp)*16 + (xp&15)
__device__ unsigned long long g_C[(size_t)VH * XB * 128 * 16];

__device__ __forceinline__ size_t cidx(int y, int xp, int zp) {
    return ((size_t)(y * XB + (xp >> 4)) * 128 + zp) * 16 + (xp & 15);
}

// ---------------------------------------------------------------------------
// Pass 1 (unchanged from R10): block = (y, 32-x group), 256 threads.
// ---------------------------------------------------------------------------
__global__ void __launch_bounds__(256) pass1_kernel(const float* __restrict__ fv,
                                                    const float* __restrict__ lmv) {
    int blk  = blockIdx.x;            // y*XB + xb
    int y    = blk / XB;
    int xb   = blk - y * XB;
    int lane = threadIdx.x & 31;
    int wid  = threadIdx.x >> 5;
    int x    = (xb << 5) + lane;

    const float* p = fv + (size_t)y * VW + x;

    float e[32];
    float s = 0.f;
#pragma unroll
    for (int i = 0; i < 32; i++) {
        int z = (wid << 5) + i;
        e[i] = __expf(p[(size_t)z * NPIX]);
        s += e[i];
    }

    __shared__ float part[8][32];
    part[wid][lane] = s;
    __syncthreads();

    float tot = 0.f;
#pragma unroll
    for (int w = 0; w < 8; w++) tot += part[w][lane];

    float mv = lmv[y * VW + x];
    float K  = (fmaxf(mv, 0.f) + 0.01f) / tot;

    unsigned long long* dst = g_C + ((size_t)blk * 128 + (wid << 4)) * 16 + (lane >> 1);
    bool even = (lane & 1) == 0;
#pragma unroll
    for (int i = 0; i < 16; i++) {
        __half2 h = __floats2half2_rn(e[2 * i] * K, e[2 * i + 1] * K);
        unsigned int u = *(unsigned int*)&h;
        unsigned int v = __shfl_xor_sync(0xffffffffu, u, 1);
        if (even) dst[(size_t)i * 16] =
            (unsigned long long)u | ((unsigned long long)v << 32);
    }
}

// ---------------------------------------------------------------------------
// Pass 2: 2 independent points per thread (ILP) over the quad-cell volume.
// ---------------------------------------------------------------------------
__device__ __forceinline__ float pickq(unsigned long long c, int sh) {
    unsigned short bits = (unsigned short)(c >> sh);
    return __half2float(__ushort_as_half(bits));
}

struct Proj { float wx, wy, wz; };

__device__ __forceinline__ float sample_point(const float* __restrict__ pts, int i,
                                              float fx, float fy, float cx, float cy,
                                              float Wimg, float Himg,
                                              float dmin, float dscale) {
    float X = pts[3 * i + 0];
    float Y = pts[3 * i + 1];
    float Z = pts[3 * i + 2];

    float px = fx * X + cx * Z;
    float py = fy * Y + cy * Z;
    float inv_e = 1.0f / (Z + 1e-10f);
    float inv = 1.0f / Z;

    float gx = (px * inv_e / Wimg - 0.5f) * 2.0f;
    float gy = (py * inv_e / Himg - 0.5f) * 2.0f;
    float gz = ((inv - dmin) * dscale - 0.5f) * 2.0f;

    float fxc = fminf(fmaxf((gx + 1.0f) * 0.5f * (float)(VW - 1), 0.0f), (float)(VW - 1));
    float fyc = fminf(fmaxf((gy + 1.0f) * 0.5f * (float)(VH - 1), 0.0f), (float)(VH - 1));
    float fzc = fminf(fmaxf((gz + 1.0f) * 0.5f * (float)(VD - 1), 0.0f), (float)(VD - 1));

    int x0 = (int)floorf(fxc); int x1 = min(x0 + 1, VW - 1);
    int y0 = (int)floorf(fyc); int y1 = min(y0 + 1, VH - 1);
    int z0 = (int)floorf(fzc); int z1 = min(z0 + 1, VD - 1);
    float wx = fxc - (float)x0;
    float wy = fyc - (float)y0;
    float wz = fzc - (float)z0;

    int xpA = x0 >> 1, xpB = x1 >> 1;
    int zpA = z0 >> 1, zpB = z1 >> 1;
    bool xd = (xpB != xpA);
    bool zd = (zpB != zpA);
    int s00 = (x0 & 1) * 32 + (z0 & 1) * 16;
    int s10 = (x1 & 1) * 32 + (z0 & 1) * 16;
    int s01 = (x0 & 1) * 32 + (z1 & 1) * 16;
    int s11 = (x1 & 1) * 32 + (z1 & 1) * 16;

    unsigned long long aAA = g_C[cidx(y0, xpA, zpA)];
    unsigned long long aBA = xd ? g_C[cidx(y0, xpB, zpA)] : aAA;
    unsigned long long aAB = zd ? g_C[cidx(y0, xpA, zpB)] : aAA;
    unsigned long long aBB = (xd && zd) ? g_C[cidx(y0, xpB, zpB)]
                                        : (xd ? aBA : (zd ? aAB : aAA));
    unsigned long long bAA = g_C[cidx(y1, xpA, zpA)];
    unsigned long long bBA = xd ? g_C[cidx(y1, xpB, zpA)] : bAA;
    unsigned long long bAB = zd ? g_C[cidx(y1, xpA, zpB)] : bAA;
    unsigned long long bBB = (xd && zd) ? g_C[cidx(y1, xpB, zpB)]
                                        : (xd ? bBA : (zd ? bAB : bAA));

    float d000 = pickq(aAA, s00);
    float d001 = pickq(aBA, s10);
    float d010 = pickq(bAA, s00);
    float d011 = pickq(bBA, s10);
    float d100 = pickq(aAB, s01);
    float d101 = pickq(aBB, s11);
    float d110 = pickq(bAB, s01);
    float d111 = pickq(bBB, s11);

    float c00 = d000 + (d001 - d000) * wx;
    float c01 = d010 + (d011 - d010) * wx;
    float c10 = d100 + (d101 - d100) * wx;
    float c11 = d110 + (d111 - d110) * wx;
    float c0 = c00 + (c01 - c00) * wy;
    float c1 = c10 + (c11 - c10) * wy;
    return c0 + (c1 - c0) * wz;
}

__global__ void __launch_bounds__(256) pass2_kernel(const float* __restrict__ pts,
                                                    const float* __restrict__ intr,
                                                    const int* __restrict__ Hp,
                                                    const int* __restrict__ Wp,
                                                    const int* __restrict__ dminp,
                                                    const int* __restrict__ dmaxp,
                                                    float* __restrict__ out,
                                                    int n) {
    int t = blockIdx.x * blockDim.x + threadIdx.x;
    int half = (n + 1) >> 1;
    if (t >= half) return;

    float fx = intr[0], cx = intr[2];
    float fy = intr[4], cy = intr[5];
    float Himg = (float)(*Hp);
    float Wimg = (float)(*Wp);
    float dmin = (float)(*dminp);
    float dmax = (float)(*dmaxp);
    float dscale = 1.0f / (dmax - dmin);

    int i0 = t;
    int i1 = t + half;

    // Two fully independent sample pipelines; ptxas interleaves their
    // gathers so ~18 loads are outstanding per thread pair.
    float r0 = sample_point(pts, i0, fx, fy, cx, cy, Wimg, Himg, dmin, dscale);
    float r1 = (i1 < n) ? sample_point(pts, i1, fx, fy, cx, cy, Wimg, Himg, dmin, dscale)
                        : 0.0f;

    out[i0] = r0;
    if (i1 < n) out[i1] = r1;
}

extern "C" void kernel_launch(void* const* d_in, const int* in_sizes, int n_in,
                              void* d_out, int out_size) {
    const float* fv   = (const float*)d_in[0];  // feature_volume [1,1,256,240,320]
    const float* lmv  = (const float*)d_in[1];  // learnable_max_value [1,1,1,240,320]
    const float* intr = (const float*)d_in[2];  // [1,3,3]
    const float* pts  = (const float*)d_in[3];  // [1,8192,128,3]
    const int*   Hp   = (const int*)d_in[4];
    const int*   Wp   = (const int*)d_in[5];
    const int*   dmin = (const int*)d_in[6];
    const int*   dmax = (const int*)d_in[7];

    pass1_kernel<<<VH * XB, 256>>>(fv, lmv);   // 2400 blocks

    int n = out_size;  // 1*8192*128 points
    int half = (n + 1) >> 1;
    pass2_kernel<<<(half + 255) / 256, 256>>>(pts, intr, Hp, Wp, dmin, dmax,
                                              (float*)d_out, n);
}